// round 16
// baseline (speedup 1.0000x reference)
#include <cuda_runtime.h>
#include <cuda_bf16.h>
#include <math.h>
#include <stdint.h>

#define BB 32
#define NN 1024
#define MM 1024
#define DD 128

#define TILE 128
#define KC   8
#define LDT  132

#define KB   16     // K per pipeline chunk
#define PA   24     // u16 pitch for [128 rows][16 k] tiles
#define PB   136    // u16 pitch for [16 rows][128 cols] tiles

// ---- scratch (static device globals; no allocation). uint4 base type for 16B align.
__device__ uint4 g_Wh4[(size_t)BB * NN * MM / 8];   // w hi plane (bf16)
__device__ uint4 g_Wl4[(size_t)BB * NN * MM / 8];   // w lo plane
__device__ uint4 g_Xch4[(size_t)BB * NN * DD / 8];  // Xc hi
__device__ uint4 g_Xcl4[(size_t)BB * NN * DD / 8];  // Xc lo
__device__ uint4 g_Yh4[(size_t)BB * MM * DD / 8];
__device__ uint4 g_Yl4[(size_t)BB * MM * DD / 8];
__device__ uint4 g_Xh4[(size_t)BB * NN * DD / 8];
__device__ uint4 g_Xl4[(size_t)BB * NN * DD / 8];
__device__ float g_rsp[8][BB * NN];                 // per-m-tile row-sum partials
__device__ float g_csp[8][BB * MM];                 // per-n-tile col-sum partials

#define UNPACK8(dst, v0, v1) \
    { dst[0]=v0.x; dst[1]=v0.y; dst[2]=v0.z; dst[3]=v0.w; \
      dst[4]=v1.x; dst[5]=v1.y; dst[6]=v1.z; dst[7]=v1.w; }

__device__ __forceinline__ void mm_step(const float (*As)[LDT], const float (*Bs)[LDT],
                                        int ty, int tx, float acc[8][8]) {
#pragma unroll
    for (int k = 0; k < KC; k++) {
        float4 a0 = *(const float4*)(&As[k][ty * 8]);
        float4 a1 = *(const float4*)(&As[k][ty * 8 + 4]);
        float4 b0 = *(const float4*)(&Bs[k][tx * 8]);
        float4 b1 = *(const float4*)(&Bs[k][tx * 8 + 4]);
        float av[8]; UNPACK8(av, a0, a1);
        float bv[8]; UNPACK8(bv, b0, b1);
#pragma unroll
        for (int r = 0; r < 8; r++)
#pragma unroll
            for (int c = 0; c < 8; c++)
                acc[r][c] = fmaf(av[r], bv[c], acc[r][c]);
    }
}

// ============================================================================
// polynomial softplus + exp on the FMA pipe (NO MUFU)
// ============================================================================
__device__ __forceinline__ void softplus_exp(float z, float& s, float& w) {
    z = fmaxf(z, -87.0f);
    float t  = fmaf(z, 1.4426950408889634f, 12582912.0f);
    int   ii = __float_as_int(t) - 0x4B400000;
    float fi = t - 12582912.0f;
    float f  = fmaf(fi, -0.693359375f, z);
    f = fmaf(fi, 2.12194440e-4f, f);
    float p = fmaf(f, 1.3888889e-3f, 8.3333333e-3f);
    p = fmaf(p, f, 4.1666667e-2f);
    p = fmaf(p, f, 0.16666667f);
    p = fmaf(p, f, 0.5f);
    p = fmaf(p, f, 1.0f);
    p = fmaf(p, f, 1.0f);
    float ez = p * __int_as_float((ii + 127) << 23);
    w = 1.0f + ez;
    int   bi = __float_as_int(w);
    int   ee = (bi - 0x3F3504F3) >> 23;
    float mm = __int_as_float(bi - (ee << 23));
    float x  = mm - 1.0f;
    float q = fmaf(x, -0.1f, 0.11111111f);
    q = fmaf(q, x, -0.125f);
    q = fmaf(q, x, 0.14285714f);
    q = fmaf(q, x, -0.16666667f);
    q = fmaf(q, x, 0.2f);
    q = fmaf(q, x, -0.25f);
    q = fmaf(q, x, 0.33333333f);
    q = fmaf(q, x, -0.5f);
    q = fmaf(q, x, 1.0f);
    q = q * x;
    s = fmaf((float)ee, 0.69314718f, q) - 0.5f;
}

// ============================================================================
// bf16 split / mma / ldmatrix / cp.async helpers
// ============================================================================
__device__ __forceinline__ uint32_t smem_u32(const void* p) {
    uint32_t a;
    asm("{ .reg .u64 t; cvta.to.shared.u64 t, %1; cvt.u32.u64 %0, t; }"
        : "=r"(a) : "l"(p));
    return a;
}

__device__ __forceinline__ void split4(float4 v, uint32_t& h0, uint32_t& h1,
                                       uint32_t& l0, uint32_t& l1) {
    __nv_bfloat162 a = __floats2bfloat162_rn(v.x, v.y);
    __nv_bfloat162 c = __floats2bfloat162_rn(v.z, v.w);
    float r0 = v.x - __bfloat162float(__low2bfloat16(a));
    float r1 = v.y - __bfloat162float(__high2bfloat16(a));
    float r2 = v.z - __bfloat162float(__low2bfloat16(c));
    float r3 = v.w - __bfloat162float(__high2bfloat16(c));
    __nv_bfloat162 e = __floats2bfloat162_rn(r0, r1);
    __nv_bfloat162 f = __floats2bfloat162_rn(r2, r3);
    h0 = *reinterpret_cast<uint32_t*>(&a);
    h1 = *reinterpret_cast<uint32_t*>(&c);
    l0 = *reinterpret_cast<uint32_t*>(&e);
    l1 = *reinterpret_cast<uint32_t*>(&f);
}

__device__ __forceinline__ void split2(float w0, float w1, uint32_t& h, uint32_t& l) {
    __nv_bfloat162 a = __floats2bfloat162_rn(w0, w1);
    float r0 = w0 - __bfloat162float(__low2bfloat16(a));
    float r1 = w1 - __bfloat162float(__high2bfloat16(a));
    __nv_bfloat162 e = __floats2bfloat162_rn(r0, r1);
    h = *reinterpret_cast<uint32_t*>(&a);
    l = *reinterpret_cast<uint32_t*>(&e);
}

__device__ __forceinline__ void mmab(float* c, const uint32_t* a,
                                     uint32_t b0, uint32_t b1) {
    asm volatile(
        "mma.sync.aligned.m16n8k16.row.col.f32.bf16.bf16.f32 "
        "{%0,%1,%2,%3}, {%4,%5,%6,%7}, {%8,%9}, {%0,%1,%2,%3};"
        : "+f"(c[0]), "+f"(c[1]), "+f"(c[2]), "+f"(c[3])
        : "r"(a[0]), "r"(a[1]), "r"(a[2]), "r"(a[3]), "r"(b0), "r"(b1));
}

__device__ __forceinline__ void ldsm4(uint32_t* r, uint32_t a) {
    asm volatile("ldmatrix.sync.aligned.m8n8.x4.shared.b16 {%0,%1,%2,%3}, [%4];"
        : "=r"(r[0]), "=r"(r[1]), "=r"(r[2]), "=r"(r[3]) : "r"(a));
}
__device__ __forceinline__ void ldsm4t(uint32_t* r, uint32_t a) {
    asm volatile("ldmatrix.sync.aligned.m8n8.x4.trans.shared.b16 {%0,%1,%2,%3}, [%4];"
        : "=r"(r[0]), "=r"(r[1]), "=r"(r[2]), "=r"(r[3]) : "r"(a));
}

__device__ __forceinline__ void cpa16(uint32_t s, const void* g) {
    asm volatile("cp.async.ca.shared.global [%0], [%1], 16;" :: "r"(s), "l"(g));
}
#define CP_COMMIT() asm volatile("cp.async.commit_group;" ::: "memory")
#define CP_WAIT1()  asm volatile("cp.async.wait_group 1;" ::: "memory")

#define MMA3(C, AH, AL, B0H, B1H, B0L, B1L) \
    { mmab(C, AH, B0H, B1H); mmab(C, AL, B0H, B1H); mmab(C, AH, B0L, B1L); }

// ============================================================================
// K0: split Ys and Xs into bf16 hi/lo planes
// ============================================================================
__global__ void __launch_bounds__(256)
k_prep(const float* __restrict__ Ys, const float* __restrict__ Xs) {
    const int idx = blockIdx.x * 256 + threadIdx.x;
    const float4* src;
    uint2 *dh, *dl;
    if (blockIdx.y == 0) {
        src = (const float4*)Ys; dh = (uint2*)g_Yh4; dl = (uint2*)g_Yl4;
    } else {
        src = (const float4*)Xs; dh = (uint2*)g_Xh4; dl = (uint2*)g_Xl4;
    }
    float4 v = src[idx];
    uint32_t h0, h1, l0, l1;
    split4(v, h0, h1, l0, l1);
    dh[idx] = make_uint2(h0, h1);
    dl[idx] = make_uint2(l0, l1);
}

// ============================================================================
// K1: Xc = Xs * tanh(W @ A_w^T + A_b) -> bf16 hi/lo planes
// ============================================================================
__global__ void __launch_bounds__(256, 2)
k_coeff(const float* __restrict__ W, const float* __restrict__ Aw,
        const float* __restrict__ Ab, const float* __restrict__ Xs) {
    __shared__ __align__(16) float As[2][KC][LDT];
    __shared__ __align__(16) float Bs[2][KC][LDT];
    const int t  = threadIdx.x;
    const int tx = t & 15, ty = t >> 4;
    const int li = t >> 1, lk4 = (t & 1) * 4;
    const int i0 = blockIdx.x * TILE;

    const float* aptr = W  + (size_t)(i0 + li) * DD + lk4;
    const float* bptr = Aw + (size_t)li * DD + lk4;

    float acc[8][8];
#pragma unroll
    for (int r = 0; r < 8; r++)
#pragma unroll
        for (int c = 0; c < 8; c++) acc[r][c] = 0.0f;

    {
        float4 ra = *(const float4*)aptr;
        float4 rb = *(const float4*)bptr;
        As[0][lk4+0][li]=ra.x; As[0][lk4+1][li]=ra.y; As[0][lk4+2][li]=ra.z; As[0][lk4+3][li]=ra.w;
        Bs[0][lk4+0][li]=rb.x; Bs[0][lk4+1][li]=rb.y; Bs[0][lk4+2][li]=rb.z; Bs[0][lk4+3][li]=rb.w;
    }
    __syncthreads();

    const int KT = DD / KC;
    int st = 0;
    for (int kt = 0; kt < KT; ++kt) {
        float4 na = make_float4(0,0,0,0), nb = make_float4(0,0,0,0);
        const bool nxt = (kt + 1 < KT);
        if (nxt) {
            na = *(const float4*)(aptr + (kt + 1) * KC);
            nb = *(const float4*)(bptr + (kt + 1) * KC);
        }
        mm_step(As[st], Bs[st], ty, tx, acc);
        if (nxt) {
            int s2 = st ^ 1;
            As[s2][lk4+0][li]=na.x; As[s2][lk4+1][li]=na.y; As[s2][lk4+2][li]=na.z; As[s2][lk4+3][li]=na.w;
            Bs[s2][lk4+0][li]=nb.x; Bs[s2][lk4+1][li]=nb.y; Bs[s2][lk4+2][li]=nb.z; Bs[s2][lk4+3][li]=nb.w;
        }
        __syncthreads();
        st ^= 1;
    }

    float abv[8];
    {
        float4 b0 = *(const float4*)(Ab + tx * 8);
        float4 b1 = *(const float4*)(Ab + tx * 8 + 4);
        UNPACK8(abv, b0, b1);
    }
#pragma unroll
    for (int r = 0; r < 8; r++) {
        int gi = i0 + ty * 8 + r;
        const float4* xp = (const float4*)(Xs + (size_t)gi * DD + tx * 8);
        float4 x0 = xp[0], x1 = xp[1];
        float xv[8]; UNPACK8(xv, x0, x1);
        float4 o0, o1;
        o0.x = tanhf(acc[r][0] + abv[0]) * xv[0];
        o0.y = tanhf(acc[r][1] + abv[1]) * xv[1];
        o0.z = tanhf(acc[r][2] + abv[2]) * xv[2];
        o0.w = tanhf(acc[r][3] + abv[3]) * xv[3];
        o1.x = tanhf(acc[r][4] + abv[4]) * xv[4];
        o1.y = tanhf(acc[r][5] + abv[5]) * xv[5];
        o1.z = tanhf(acc[r][6] + abv[6]) * xv[6];
        o1.w = tanhf(acc[r][7] + abv[7]) * xv[7];
        uint32_t h0, h1, l0, l1, h2, h3, l2, l3;
        split4(o0, h0, h1, l0, l1);
        split4(o1, h2, h3, l2, l3);
        g_Xch4[(size_t)gi * 16 + tx] = make_uint4(h0, h1, h2, h3);
        g_Xcl4[(size_t)gi * 16 + tx] = make_uint4(l0, l1, l2, l3);
    }
}

// ============================================================================
// K2: s = softplus(Xc @ Ys^T) - 0.5; w planes; row/col sum partials
// ============================================================================
#define SC_STGU  12288
#define SC_STGB  (SC_STGU * 2)
#define SC_SMEMB (3 * SC_STGB)         // 73728

__global__ void __launch_bounds__(256, 2)
k_scores_b(float* __restrict__ s_out) {
    extern __shared__ __align__(16) uint16_t smu[];
    __shared__ float rpart[2][128];
    __shared__ float cpart[4][128];
    const int t = threadIdx.x, lane = t & 31, wid = t >> 5;
    const int mw = wid >> 1, nw = wid & 1;
    const int gid = lane >> 2, tig = lane & 3;
    const int n0 = blockIdx.x * 128, m0 = blockIdx.y * 128, b = blockIdx.z;

    const uint16_t* gAh = (const uint16_t*)g_Xch4 + ((size_t)b * NN + n0) * DD;
    const uint16_t* gAl = (const uint16_t*)g_Xcl4 + ((size_t)b * NN + n0) * DD;
    const uint16_t* gBh = (const uint16_t*)g_Yh4 + ((size_t)b * MM + m0) * DD;
    const uint16_t* gBl = (const uint16_t*)g_Yl4 + ((size_t)b * MM + m0) * DD;

    float acc[2][8][4];
#pragma unroll
    for (int mf = 0; mf < 2; mf++)
#pragma unroll
        for (int nf = 0; nf < 8; nf++)
#pragma unroll
            for (int i = 0; i < 4; i++) acc[mf][nf][i] = 0.0f;

    const uint32_t sb = smem_u32(smu);
    const int row = t >> 1, ko = (t & 1) * 8;
    const int midx = lane >> 3, rw = lane & 7;
    uint32_t aA[2], aB[4];
    {
        const int koA = (midx >> 1) * 8;
        aA[0] = sb + ((mw * 32 +      (midx & 1) * 8 + rw) * PA + koA) * 2;
        aA[1] = sb + ((mw * 32 + 16 + (midx & 1) * 8 + rw) * PA + koA) * 2;
        const int koB = (midx & 1) * 8;
#pragma unroll
        for (int q = 0; q < 4; q++)
            aB[q] = sb + (6144 + (nw * 64 + q * 16 + (midx >> 1) * 8 + rw) * PA + koB) * 2;
    }

#define SC_ISSUE(stg, kcc)                                                    \
    { const uint32_t sba = sb + (stg) * SC_STGB + (row * PA + ko) * 2;        \
      const size_t go = (size_t)row * DD + (kcc) * 16 + ko;                   \
      cpa16(sba,            gAh + go);                                        \
      cpa16(sba + 3072 * 2, gAl + go);                                        \
      cpa16(sba + 6144 * 2, gBh + go);                                        \
      cpa16(sba + 9216 * 2, gBl + go); }

    SC_ISSUE(0, 0); CP_COMMIT();
    SC_ISSUE(1, 1); CP_COMMIT();

    const int NCH = DD / KB;   // 8
    int st = 0;
    for (int kc = 0; kc < NCH; ++kc) {
        CP_WAIT1();
        __syncthreads();
        if (kc + 2 < NCH) {
            int s2 = st + 2; if (s2 >= 3) s2 -= 3;
            SC_ISSUE(s2, kc + 2);
        }
        CP_COMMIT();

        const uint32_t stb = st * SC_STGB;
        uint32_t ah0[4], al0[4], ah1[4], al1[4];
        ldsm4(ah0, aA[0] + stb); ldsm4(al0, aA[0] + stb + 6144);
        ldsm4(ah1, aA[1] + stb); ldsm4(al1, aA[1] + stb + 6144);
#pragma unroll
        for (int q = 0; q < 4; q++) {
            uint32_t bh[4], bl[4];
            ldsm4(bh, aB[q] + stb); ldsm4(bl, aB[q] + stb + 6144);
            MMA3(acc[0][2*q],   ah0, al0, bh[0], bh[1], bl[0], bl[1]);
            MMA3(acc[0][2*q+1], ah0, al0, bh[2], bh[3], bl[2], bl[3]);
            MMA3(acc[1][2*q],   ah1, al1, bh[0], bh[1], bl[0], bl[1]);
            MMA3(acc[1][2*q+1], ah1, al1, bh[2], bh[3], bl[2], bl[3]);
        }
        ++st; if (st == 3) st = 0;
    }

    // epilogue: s store, w planes, row/col partials
    uint32_t* Wh = (uint32_t*)g_Wh4;
    uint32_t* Wl = (uint32_t*)g_Wl4;
    float rp[2][2] = {{0,0},{0,0}};
    float cpA[8], cpB[8];
#pragma unroll
    for (int i = 0; i < 8; i++) { cpA[i] = 0.0f; cpB[i] = 0.0f; }

#pragma unroll
    for (int mf = 0; mf < 2; ++mf) {
        const int r1 = n0 + mw * 32 + mf * 16 + gid;
        const int r2 = r1 + 8;
#pragma unroll
        for (int nf = 0; nf < 8; ++nf) {
            const int cc = m0 + nw * 64 + nf * 8 + tig * 2;
            float s0, w0, s1, w1, s2, w2, s3, w3;
            softplus_exp(acc[mf][nf][0], s0, w0);
            softplus_exp(acc[mf][nf][1], s1, w1);
            softplus_exp(acc[mf][nf][2], s2, w2);
            softplus_exp(acc[mf][nf][3], s3, w3);
            const size_t o1 = ((size_t)b * NN + r1) * MM + cc;
            const size_t o2 = ((size_t)b * NN + r2) * MM + cc;
            *(float2*)(s_out + o1) = make_float2(s0, s1);
            *(float2*)(s_out + o2) = make_float2(s2, s3);
            uint32_t h, l;
            split2(w0, w1, h, l); Wh[o1 >> 1] = h; Wl[o1 >> 1] = l;
            split2(w2, w3, h, l); Wh[o2 >> 1] = h; Wl[o2 >> 1] = l;
            rp[mf][0] += w0 + w1;
            rp[mf][1] += w2 + w3;
            cpA[nf] += w0 + w2;
            cpB[nf] += w1 + w3;
        }
    }

    // row partials: reduce over tig (lane bits 0-1)
#pragma unroll
    for (int mf = 0; mf < 2; ++mf) {
#pragma unroll
        for (int j = 0; j < 2; ++j) {
            rp[mf][j] += __shfl_xor_sync(0xFFFFFFFFu, rp[mf][j], 1);
            rp[mf][j] += __shfl_xor_sync(0xFFFFFFFFu, rp[mf][j], 2);
        }
    }
    // col partials: reduce over gid (lane bits 2-4)
#pragma unroll
    for (int nf = 0; nf < 8; ++nf) {
        cpA[nf] += __shfl_xor_sync(0xFFFFFFFFu, cpA[nf], 4);
        cpA[nf] += __shfl_xor_sync(0xFFFFFFFFu, cpA[nf], 8);
        cpA[nf] += __shfl_xor_sync(0xFFFFFFFFu, cpA[nf], 16);
        cpB[nf] += __shfl_xor_sync(0xFFFFFFFFu, cpB[nf], 4);
        cpB[nf] += __shfl_xor_sync(0xFFFFFFFFu, cpB[nf], 8);
        cpB[nf] += __shfl_xor_sync(0xFFFFFFFFu, cpB[nf], 16);
    }
    __syncthreads();
    if (tig == 0) {
#pragma unroll
        for (int mf = 0; mf < 2; ++mf) {
            rpart[nw][mw * 32 + mf * 16 + gid]     = rp[mf][0];
            rpart[nw][mw * 32 + mf * 16 + gid + 8] = rp[mf][1];
        }
    }
    if (gid == 0) {
#pragma unroll
        for (int nf = 0; nf < 8; ++nf) {
            cpart[mw][nw * 64 + nf * 8 + tig * 2]     = cpA[nf];
            cpart[mw][nw * 64 + nf * 8 + tig * 2 + 1] = cpB[nf];
        }
    }
    __syncthreads();
    if (t < 128) {
        g_rsp[blockIdx.y][b * NN + n0 + t] = rpart[0][t] + rpart[1][t];
        g_csp[blockIdx.x][b * MM + m0 + t] =
            cpart[0][t] + cpart[1][t] + cpart[2][t] + cpart[3][t];
    }
}

// ============================================================================
// K3: attention_x = (w @ Ys) / rowsum(w)   — pure cp.async loaders
// ============================================================================
#define AX_STGU  10496
#define AX_STGB  (AX_STGU * 2)
#define AX_SMEMB (3 * AX_STGB)         // 62976

__global__ void __launch_bounds__(256, 2)
k_attnx_b(float* __restrict__ outx) {
    extern __shared__ __align__(16) uint16_t smu[];
    __shared__ float rs[128];
    const int t = threadIdx.x, lane = t & 31, wid = t >> 5;
    const int mw = wid >> 1, nw = wid & 1;
    const int gid = lane >> 2, tig = lane & 3;
    const int n0 = blockIdx.x * 128, b = blockIdx.z;

    const uint16_t* gWh = (const uint16_t*)g_Wh4 + ((size_t)b * NN + n0) * MM;
    const uint16_t* gWl = (const uint16_t*)g_Wl4 + ((size_t)b * NN + n0) * MM;
    const uint16_t* gYh = (const uint16_t*)g_Yh4 + (size_t)b * MM * DD;
    const uint16_t* gYl = (const uint16_t*)g_Yl4 + (size_t)b * MM * DD;

    float acc[2][8][4];
#pragma unroll
    for (int mf = 0; mf < 2; mf++)
#pragma unroll
        for (int nf = 0; nf < 8; nf++)
#pragma unroll
            for (int i = 0; i < 4; i++) acc[mf][nf][i] = 0.0f;

    const uint32_t sb = smem_u32(smu);
    const int row = t >> 1, ko = (t & 1) * 8;       // A loader
    const int rb = t >> 4, seg = (t & 15) * 8;      // B loader
    const int midx = lane >> 3, rw = lane & 7;
    uint32_t aA[2], aB[4];
    {
        const int koA = (midx >> 1) * 8;
        aA[0] = sb + ((mw * 32 +      (midx & 1) * 8 + rw) * PA + koA) * 2;
        aA[1] = sb + ((mw * 32 + 16 + (midx & 1) * 8 + rw) * PA + koA) * 2;
#pragma unroll
        for (int q = 0; q < 4; q++)
            aB[q] = sb + (6144 + ((midx & 1) * 8 + rw) * PB
                          + nw * 64 + q * 16 + (midx >> 1) * 8) * 2;
    }

#define AX_ISSUE(stg, kcc)                                                    \
    { const uint32_t s0 = sb + (stg) * AX_STGB;                               \
      const size_t ga = (size_t)row * MM + (kcc) * 16 + ko;                   \
      const uint32_t sa = s0 + (row * PA + ko) * 2;                           \
      cpa16(sa,            gWh + ga);                                         \
      cpa16(sa + 3072 * 2, gWl + ga);                                         \
      const size_t gb = (size_t)((kcc) * 16 + rb) * DD + seg;                 \
      const uint32_t sbx = s0 + (6144 + rb * PB + seg) * 2;                   \
      cpa16(sbx,            gYh + gb);                                        \
      cpa16(sbx + 2176 * 2, gYl + gb); }

    AX_ISSUE(0, 0); CP_COMMIT();
    AX_ISSUE(1, 1); CP_COMMIT();

    if (t < 128) {
        float v = 0.0f;
#pragma unroll
        for (int q = 0; q < 8; q++) v += g_rsp[q][b * NN + n0 + t];
        rs[t] = v;
    }

    const int NCH = MM / KB;   // 64
    int st = 0;
    for (int kc = 0; kc < NCH; ++kc) {
        CP_WAIT1();
        __syncthreads();
        if (kc + 2 < NCH) {
            int s2 = st + 2; if (s2 >= 3) s2 -= 3;
            AX_ISSUE(s2, kc + 2);
        }
        CP_COMMIT();

        const uint32_t stb = st * AX_STGB;
        uint32_t ah0[4], al0[4], ah1[4], al1[4];
        ldsm4(ah0, aA[0] + stb); ldsm4(al0, aA[0] + stb + 6144);
        ldsm4(ah1, aA[1] + stb); ldsm4(al1, aA[1] + stb + 6144);
#pragma unroll
        for (int q = 0; q < 4; q++) {
            uint32_t bh[4], bl[4];
            ldsm4t(bh, aB[q] + stb); ldsm4t(bl, aB[q] + stb + 4352);
            MMA3(acc[0][2*q],   ah0, al0, bh[0], bh[1], bl[0], bl[1]);
            MMA3(acc[0][2*q+1], ah0, al0, bh[2], bh[3], bl[2], bl[3]);
            MMA3(acc[1][2*q],   ah1, al1, bh[0], bh[1], bl[0], bl[1]);
            MMA3(acc[1][2*q+1], ah1, al1, bh[2], bh[3], bl[2], bl[3]);
        }
        ++st; if (st == 3) st = 0;
    }

#pragma unroll
    for (int mf = 0; mf < 2; ++mf) {
        const int lr1 = mw * 32 + mf * 16 + gid;
        const int lr2 = lr1 + 8;
        const float ri1 = 1.0f / rs[lr1];
        const float ri2 = 1.0f / rs[lr2];
#pragma unroll
        for (int nf = 0; nf < 8; ++nf) {
            const int cc = nw * 64 + nf * 8 + tig * 2;
            *(float2*)(outx + ((size_t)b * NN + n0 + lr1) * DD + cc) =
                make_float2(acc[mf][nf][0] * ri1, acc[mf][nf][1] * ri1);
            *(float2*)(outx + ((size_t)b * NN + n0 + lr2) * DD + cc) =
                make_float2(acc[mf][nf][2] * ri2, acc[mf][nf][3] * ri2);
        }
    }
}

// ============================================================================
// K4: attention_y = (w^T @ Xs) / colsum(w)   — pure cp.async loaders
// ============================================================================
#define AY_STGU  8704
#define AY_STGB  (AY_STGU * 2)
#define AY_SMEMB (3 * AY_STGB)         // 52224

__global__ void __launch_bounds__(256, 2)
k_attny_b(float* __restrict__ outy) {
    extern __shared__ __align__(16) uint16_t smu[];
    __shared__ float cs[128];
    const int t = threadIdx.x, lane = t & 31, wid = t >> 5;
    const int mw = wid >> 1, nw = wid & 1;
    const int gid = lane >> 2, tig = lane & 3;
    const int m0 = blockIdx.x * 128, b = blockIdx.z;

    const uint16_t* gWh = (const uint16_t*)g_Wh4 + (size_t)b * NN * MM + m0;
    const uint16_t* gWl = (const uint16_t*)g_Wl4 + (size_t)b * NN * MM + m0;
    const uint16_t* gXh = (const uint16_t*)g_Xh4 + (size_t)b * NN * DD;
    const uint16_t* gXl = (const uint16_t*)g_Xl4 + (size_t)b * NN * DD;

    float acc[2][8][4];
#pragma unroll
    for (int mf = 0; mf < 2; mf++)
#pragma unroll
        for (int nf = 0; nf < 8; nf++)
#pragma unroll
            for (int i = 0; i < 4; i++) acc[mf][nf][i] = 0.0f;

    const uint32_t sb = smem_u32(smu);
    const int rb = t >> 4, seg = (t & 15) * 8;
    const int midx = lane >> 3, rw = lane & 7;
    uint32_t aA[2], aB[4];
    {
#pragma unroll
        for (int mf = 0; mf < 2; mf++)
            aA[mf] = sb + (((midx >> 1) * 8 + rw) * PB
                           + mw * 32 + mf * 16 + (midx & 1) * 8) * 2;
#pragma unroll
        for (int q = 0; q < 4; q++)
            aB[q] = sb + (4352 + ((midx & 1) * 8 + rw) * PB
                          + nw * 64 + q * 16 + (midx >> 1) * 8) * 2;
    }

#define AY_ISSUE(stg, kcc)                                                    \
    { const uint32_t s0 = sb + (stg) * AY_STGB;                               \
      const size_t ga = (size_t)((kcc) * 16 + rb) * MM + seg;                 \
      const uint32_t sa = s0 + (rb * PB + seg) * 2;                           \
      cpa16(sa,            gWh + ga);                                         \
      cpa16(sa + 2176 * 2, gWl + ga);                                         \
      const size_t gb = (size_t)((kcc) * 16 + rb) * DD + seg;                 \
      const uint32_t sbx = s0 + (4352 + rb * PB + seg) * 2;                   \
      cpa16(sbx,            gXh + gb);                                        \
      cpa16(sbx + 2176 * 2, gXl + gb); }

    AY_ISSUE(0, 0); CP_COMMIT();
    AY_ISSUE(1, 1); CP_COMMIT();

    if (t < 128) {
        float v = 0.0f;
#pragma unroll
        for (int q = 0; q < 8; q++) v += g_csp[q][b * MM + m0 + t];
        cs[t] = v;
    }

    const int NCH = NN / KB;   // 64
    int st = 0;
    for (int kc = 0; kc < NCH; ++kc) {
        CP_WAIT1();
        __syncthreads();
        if (kc + 2 < NCH) {
            int s2 = st + 2; if (s2 >= 3) s2 -= 3;
            AY_ISSUE(s2, kc + 2);
        }
        CP_COMMIT();

        const uint32_t stb = st * AY_STGB;
        uint32_t ah0[4], al0[4], ah1[4], al1[4];
        ldsm4t(ah0, aA[0] + stb); ldsm4t(al0, aA[0] + stb + 4352);
        ldsm4t(ah1, aA[1] + stb); ldsm4t(al1, aA[1] + stb + 4352);
#pragma unroll
        for (int q = 0; q < 4; q++) {
            uint32_t bh[4], bl[4];
            ldsm4t(bh, aB[q] + stb); ldsm4t(bl, aB[q] + stb + 4352);
            MMA3(acc[0][2*q],   ah0, al0, bh[0], bh[1], bl[0], bl[1]);
            MMA3(acc[0][2*q+1], ah0, al0, bh[2], bh[3], bl[2], bl[3]);
            MMA3(acc[1][2*q],   ah1, al1, bh[0], bh[1], bl[0], bl[1]);
            MMA3(acc[1][2*q+1], ah1, al1, bh[2], bh[3], bl[2], bl[3]);
        }
        ++st; if (st == 3) st = 0;
    }

#pragma unroll
    for (int mf = 0; mf < 2; ++mf) {
        const int lr1 = mw * 32 + mf * 16 + gid;
        const int lr2 = lr1 + 8;
        const float ci1 = 1.0f / cs[lr1];
        const float ci2 = 1.0f / cs[lr2];
#pragma unroll
        for (int nf = 0; nf < 8; ++nf) {
            const int cc = nw * 64 + nf * 8 + tig * 2;
            *(float2*)(outy + ((size_t)b * MM + m0 + lr1) * DD + cc) =
                make_float2(acc[mf][nf][0] * ci1, acc[mf][nf][1] * ci1);
            *(float2*)(outy + ((size_t)b * MM + m0 + lr2) * DD + cc) =
                make_float2(acc[mf][nf][2] * ci2, acc[mf][nf][3] * ci2);
        }
    }
}

// ============================================================================
// launch
// ============================================================================
extern "C" void kernel_launch(void* const* d_in, const int* in_sizes, int n_in,
                              void* d_out, int out_size) {
    const float* Xs = (const float*)d_in[0];
    const float* Ys = (const float*)d_in[1];
    const float* W  = (const float*)d_in[2];
    const float* Aw = (const float*)d_in[3];
    const float* Ab = (const float*)d_in[4];

    float* outx = (float*)d_out;                       // [B,N,D]
    float* outy = outx + (size_t)BB * NN * DD;         // [B,M,D]
    float* s    = outy + (size_t)BB * MM * DD;         // [B,N,M]

    cudaFuncSetAttribute(k_scores_b, cudaFuncAttributeMaxDynamicSharedMemorySize,
                         SC_SMEMB);
    cudaFuncSetAttribute(k_attnx_b, cudaFuncAttributeMaxDynamicSharedMemorySize,
                         AX_SMEMB);
    cudaFuncSetAttribute(k_attny_b, cudaFuncAttributeMaxDynamicSharedMemorySize,
                         AY_SMEMB);

    k_prep    <<<dim3(BB * MM * DD / 1024, 2), 256>>>(Ys, Xs);
    k_coeff   <<<BB * NN / TILE, 256>>>(W, Aw, Ab, Xs);
    k_scores_b<<<dim3(NN / 128, MM / 128, BB), 256, SC_SMEMB>>>(s);
    k_attnx_b <<<dim3(NN / 128, 1, BB), 256, AX_SMEMB>>>(outx);
    k_attny_b <<<dim3(MM / 128, 1, BB), 256, AY_SMEMB>>>(outy);
}